// round 11
// baseline (speedup 1.0000x reference)
#include <cuda_runtime.h>
#include <cuda_bf16.h>
#include <math.h>
#include <stdint.h>

#define Bsz  4
#define Tlen 512
#define Edim 1024
#define Vdim 32000
#define GDIM (4*Edim)           // 4096
#define MROWS (Tlen*Bsz)        // 2048
#define NBLK 128
#define LOGB (-1.0005003335835335e-3)

// ---------------- scratch ----------------
static __device__ __align__(16) __nv_bfloat16 g_xbf [MROWS * Edim];
static __device__ __align__(16) float g_gates[MROWS * GDIM];
static __device__ __align__(16) __nv_bfloat16 g_h0bf[(Tlen+1) * Bsz*Edim];
static __device__ __align__(16) __nv_bfloat16 g_h1bf[(Tlen+1) * Bsz*Edim];
static __device__ __align__(16) __nv_bfloat16 g_wih0bf[GDIM * Edim];
static __device__ __align__(16) __nv_bfloat16 g_wih1bf[GDIM * Edim];
static __device__ __align__(16) __nv_bfloat16 g_wprojbf[(size_t)Vdim * Edim];

// dedicated-waiter barrier state
static __device__ unsigned int g_slot[NBLK];
static __device__ unsigned int g_rel2;
__global__ void bar_reset() {
    if (threadIdx.x < NBLK) g_slot[threadIdx.x] = 0;
    if (threadIdx.x == 0) g_rel2 = 0;
}

// ---------------- helpers ----------------
__device__ __forceinline__ float tanh_acc(float x) {
    float ax = fabsf(x);
    float t  = expf(-2.f * ax);
    float r  = (1.f - t) / (1.f + t);
    return copysignf(r, x);
}
__device__ __forceinline__ float sigm(float x) { return 1.f / (1.f + expf(-x)); }

__device__ __forceinline__ void spin_acq(const unsigned int* p, unsigned int gen) {
    unsigned int v;
    do {
        asm volatile("ld.acquire.gpu.u32 %0, [%1];" : "=r"(v) : "l"(p) : "memory");
    } while (v < gen);
}
__device__ __forceinline__ void st_rel(unsigned int* p, unsigned int v) {
    asm volatile("st.release.gpu.u32 [%0], %1;" :: "l"(p), "r"(v) : "memory");
}

__device__ __forceinline__ unsigned long long bf2f2(uint32_t p) {
    uint32_t lo = p << 16;
    uint32_t hi = p & 0xFFFF0000u;
    unsigned long long r;
    asm("mov.b64 %0, {%1,%2};" : "=l"(r) : "r"(lo), "r"(hi));
    return r;
}
__device__ __forceinline__ void fma2(unsigned long long& acc,
                                     unsigned long long a, unsigned long long b) {
    asm("fma.rn.f32x2 %0, %1, %2, %0;" : "+l"(acc) : "l"(a), "l"(b));
}
__device__ __forceinline__ float f2sum(unsigned long long acc) {
    uint32_t lo, hi;
    asm("mov.b64 {%0,%1}, %2;" : "=r"(lo), "=r"(hi) : "l"(acc));
    return __uint_as_float(lo) + __uint_as_float(hi);
}
__device__ __forceinline__ uint32_t packbf(float a, float b) {
    __nv_bfloat162 t = __floats2bfloat162_rn(a, b);
    return *(uint32_t*)&t;
}

__device__ __forceinline__ void ldsm_x4(uint32_t& r0, uint32_t& r1, uint32_t& r2, uint32_t& r3,
                                        uint32_t addr) {
    asm volatile("ldmatrix.sync.aligned.m8n8.x4.shared.b16 {%0,%1,%2,%3}, [%4];"
                 : "=r"(r0), "=r"(r1), "=r"(r2), "=r"(r3) : "r"(addr));
}
__device__ __forceinline__ void mma_bf16(float c[4], const uint32_t a[4], const uint32_t b[2]) {
    asm volatile(
        "mma.sync.aligned.m16n8k16.row.col.f32.bf16.bf16.f32 "
        "{%0,%1,%2,%3}, {%4,%5,%6,%7}, {%8,%9}, {%0,%1,%2,%3};"
        : "+f"(c[0]), "+f"(c[1]), "+f"(c[2]), "+f"(c[3])
        : "r"(a[0]), "r"(a[1]), "r"(a[2]), "r"(a[3]), "r"(b[0]), "r"(b[1]));
}

// ---------------- fp32 -> bf16 ----------------
__global__ void f2bf_kernel(const float* __restrict__ s, __nv_bfloat16* __restrict__ d, int n) {
    int idx = (blockIdx.x * blockDim.x + threadIdx.x) * 4;
    if (idx >= n) return;
    float4 v = *(const float4*)(s + idx);
    uint2 p;
    p.x = packbf(v.x, v.y); p.y = packbf(v.z, v.w);
    *(uint2*)(d + idx) = p;
}

// ---------------- embedding ----------------
__global__ void embed_kernel(const int* __restrict__ tokens, const float* __restrict__ emb) {
    int id = blockIdx.x * blockDim.x + threadIdx.x;
    const int EV = Edim / 4;
    if (id >= MROWS * EV) return;
    int e4 = id % EV;
    int m  = id / EV;
    int b  = m & 3, t = m >> 2;
    int tok = tokens[b * Tlen + t];
    float4 v = ((const float4*)(emb + (size_t)tok * Edim))[e4];
    uint2 p; p.x = packbf(v.x, v.y); p.y = packbf(v.z, v.w);
    *(uint2*)(g_xbf + (size_t)id * 4) = p;
}

// ---------------- hybrid GEMM (NT): C = A @ B^T (+bias) ----------------
// Per 128x128 tile, path chosen by (bx+by)%3: 2/3 tiles use bf16 mma.sync
// (tensor pipe), 1/3 use FFMA (fma pipe). With 2 blocks/SM the co-resident
// pair usually mixes paths -> both pipes busy per SM.
__global__ void __launch_bounds__(256, 2)
gemm_hybrid(const __nv_bfloat16* __restrict__ A, const __nv_bfloat16* __restrict__ B,
            float* __restrict__ C, int M, int N, int K,
            const float* __restrict__ bias1, const float* __restrict__ bias2,
            int remap)
{
    extern __shared__ char sm_[];
    const int tid  = threadIdx.x;
    const int row0 = blockIdx.x * 128;
    const int col0 = blockIdx.y * 128;
    const bool use_mma = ((blockIdx.x + blockIdx.y) % 3) != 2;

    if (use_mma) {
        // ---- bf16 mma.sync path (round-8 proven body) ----
        __nv_bfloat16* As = (__nv_bfloat16*)sm_;
        __nv_bfloat16* Bs = As + 128 * 40;
        const int wid  = tid >> 5, lane = tid & 31;
        const int g    = lane >> 2, tig = lane & 3;
        const int q    = lane >> 3, r = lane & 7;
        const int warp_m = (wid >> 2) * 64;
        const int warp_n = (wid & 3) * 32;

        const int ldr = tid >> 2;
        const int ldc = (tid & 3) * 8;

        const __nv_bfloat16* Ap0 = A + (size_t)(row0 + ldr) * K + ldc;
        const __nv_bfloat16* Ap1 = A + (size_t)(row0 + ldr + 64) * K + ldc;
        const __nv_bfloat16* Bp0 = B + (size_t)(col0 + ldr) * K + ldc;
        const __nv_bfloat16* Bp1 = B + (size_t)(col0 + ldr + 64) * K + ldc;

        const uint32_t as_base = (uint32_t)__cvta_generic_to_shared(As);
        const uint32_t bs_base = (uint32_t)__cvta_generic_to_shared(Bs);
        const uint32_t a_addr0 = as_base + (uint32_t)(((warp_m + (q & 1) * 8 + r) * 40 + (q >> 1) * 8) * 2);
        const uint32_t b_addr0 = bs_base + (uint32_t)(((warp_n + (q & 1) * 8 + r) * 40 + (q >> 1) * 8) * 2);

        float acc[16][4];
#pragma unroll
        for (int i = 0; i < 16; i++)
#pragma unroll
            for (int j = 0; j < 4; j++) acc[i][j] = 0.f;

        uint4 pa0 = *(const uint4*)Ap0;
        uint4 pa1 = *(const uint4*)Ap1;
        uint4 pb0 = *(const uint4*)Bp0;
        uint4 pb1 = *(const uint4*)Bp1;

        for (int kb = 0; kb < K; kb += 32) {
            *(uint4*)&As[ldr * 40 + ldc]        = pa0;
            *(uint4*)&As[(ldr + 64) * 40 + ldc] = pa1;
            *(uint4*)&Bs[ldr * 40 + ldc]        = pb0;
            *(uint4*)&Bs[(ldr + 64) * 40 + ldc] = pb1;
            __syncthreads();

            if (kb + 32 < K) {
                pa0 = *(const uint4*)(Ap0 + kb + 32);
                pa1 = *(const uint4*)(Ap1 + kb + 32);
                pb0 = *(const uint4*)(Bp0 + kb + 32);
                pb1 = *(const uint4*)(Bp1 + kb + 32);
            }

#pragma unroll
            for (int ks = 0; ks < 2; ks++) {
                uint32_t af[4][4], bf[4][2];
#pragma unroll
                for (int mt = 0; mt < 4; mt++)
                    ldsm_x4(af[mt][0], af[mt][1], af[mt][2], af[mt][3],
                            a_addr0 + (uint32_t)((mt * 16 * 40 + ks * 16) * 2));
#pragma unroll
                for (int bt = 0; bt < 2; bt++) {
                    uint32_t m0, m1, m2, m3;
                    ldsm_x4(m0, m1, m2, m3,
                            b_addr0 + (uint32_t)((bt * 16 * 40 + ks * 16) * 2));
                    bf[bt * 2 + 0][0] = m0; bf[bt * 2 + 1][0] = m1;
                    bf[bt * 2 + 0][1] = m2; bf[bt * 2 + 1][1] = m3;
                }
#pragma unroll
                for (int mt = 0; mt < 4; mt++)
#pragma unroll
                    for (int nt = 0; nt < 4; nt++)
                        mma_bf16(acc[mt * 4 + nt], af[mt], bf[nt]);
            }
            __syncthreads();
        }

#pragma unroll
        for (int mt = 0; mt < 4; mt++) {
            int m0 = row0 + warp_m + mt * 16 + g;
            int m1 = m0 + 8;
            int r0 = remap ? ((m0 & 3) * Tlen + (m0 >> 2)) : m0;
            int r1 = remap ? ((m1 & 3) * Tlen + (m1 >> 2)) : m1;
#pragma unroll
            for (int nt = 0; nt < 4; nt++) {
                int n = col0 + warp_n + nt * 8 + tig * 2;
                float bv0 = 0.f, bv1 = 0.f;
                if (bias1) { bv0 += bias1[n]; bv1 += bias1[n + 1]; }
                if (bias2) { bv0 += bias2[n]; bv1 += bias2[n + 1]; }
                float* c = acc[mt * 4 + nt];
                *(float2*)&C[(size_t)r0 * N + n] = make_float2(c[0] + bv0, c[1] + bv1);
                *(float2*)&C[(size_t)r1 * N + n] = make_float2(c[2] + bv0, c[3] + bv1);
            }
        }
    } else {
        // ---- FFMA path (round-6 proven body, bf16 inputs converted on load) ----
        float* Asf = (float*)sm_;           // [8][132]
        float* Bsf = Asf + 8 * 132;
        const int lr = tid >> 1;            // 0..127
        const int lc = (tid & 1) * 4;       // 0 or 4
        const int ty = tid >> 4;            // 0..15
        const int tx = tid & 15;            // 0..15

        const __nv_bfloat16* Aptr = A + (size_t)(row0 + lr) * K + lc;
        const __nv_bfloat16* Bptr = B + (size_t)(col0 + lr) * K + lc;

        float acc[8][8];
#pragma unroll
        for (int i = 0; i < 8; i++)
#pragma unroll
            for (int j = 0; j < 8; j++) acc[i][j] = 0.f;

        for (int kb = 0; kb < K; kb += 8) {
            uint2 pa = *(const uint2*)(Aptr + kb);
            uint2 pb = *(const uint2*)(Bptr + kb);
            Asf[(lc + 0) * 132 + lr] = __uint_as_float(pa.x << 16);
            Asf[(lc + 1) * 132 + lr] = __uint_as_float(pa.x & 0xFFFF0000u);
            Asf[(lc + 2) * 132 + lr] = __uint_as_float(pa.y << 16);
            Asf[(lc + 3) * 132 + lr] = __uint_as_float(pa.y & 0xFFFF0000u);
            Bsf[(lc + 0) * 132 + lr] = __uint_as_float(pb.x << 16);
            Bsf[(lc + 1) * 132 + lr] = __uint_as_float(pb.x & 0xFFFF0000u);
            Bsf[(lc + 2) * 132 + lr] = __uint_as_float(pb.y << 16);
            Bsf[(lc + 3) * 132 + lr] = __uint_as_float(pb.y & 0xFFFF0000u);
            __syncthreads();
#pragma unroll
            for (int kk = 0; kk < 8; kk++) {
                float4 a0 = *(const float4*)&Asf[kk * 132 + ty * 8];
                float4 a1 = *(const float4*)&Asf[kk * 132 + ty * 8 + 4];
                float4 b0 = *(const float4*)&Bsf[kk * 132 + tx * 8];
                float4 b1 = *(const float4*)&Bsf[kk * 132 + tx * 8 + 4];
                float a[8] = {a0.x, a0.y, a0.z, a0.w, a1.x, a1.y, a1.z, a1.w};
                float b[8] = {b0.x, b0.y, b0.z, b0.w, b1.x, b1.y, b1.z, b1.w};
#pragma unroll
                for (int i = 0; i < 8; i++)
#pragma unroll
                    for (int j = 0; j < 8; j++) acc[i][j] = fmaf(a[i], b[j], acc[i][j]);
            }
            __syncthreads();
        }

        float bsave[8];
#pragma unroll
        for (int j = 0; j < 8; j++) {
            int n = col0 + tx * 8 + j;
            float bvv = 0.f;
            if (bias1) bvv += bias1[n];
            if (bias2) bvv += bias2[n];
            bsave[j] = bvv;
        }
#pragma unroll
        for (int i = 0; i < 8; i++) {
            int m = row0 + ty * 8 + i;
            int orow = remap ? ((m & 3) * Tlen + (m >> 2)) : m;
            float* crow = C + (size_t)orow * N + col0 + tx * 8;
            float4 v0, v1;
            v0.x = acc[i][0] + bsave[0]; v0.y = acc[i][1] + bsave[1];
            v0.z = acc[i][2] + bsave[2]; v0.w = acc[i][3] + bsave[3];
            v1.x = acc[i][4] + bsave[4]; v1.y = acc[i][5] + bsave[5];
            v1.z = acc[i][6] + bsave[6]; v1.w = acc[i][7] + bsave[7];
            *(float4*)(crow)     = v0;
            *(float4*)(crow + 4) = v1;
        }
    }
}

// ---------------- persistent LSTM layer (dedicated-waiter barrier) ----------------
__global__ void __launch_bounds__(256, 1)
lstm_layer(const float* __restrict__ gih,
           const float* __restrict__ Whh,
           __nv_bfloat16* __restrict__ hbf)
{
    extern __shared__ uint32_t smu[];
    uint32_t* wsb = smu;
    uint32_t* hsb = wsb + 32 * 512;
    float*    garr = (float*)(hsb + 4 * 512);
    float*    cs   = garr + 128;

    const int blk  = blockIdx.x;
    const int e0   = blk * 8;
    const int tid  = threadIdx.x;
    const int warp = tid >> 5;
    const int lane = tid & 31;

    for (int r = warp; r < 32; r += 8) {
        int g = r >> 3, j = r & 7;
        const float* src = Whh + (size_t)(g * Edim + e0 + j) * Edim;
        for (int c = lane * 4; c < Edim; c += 128) {
            float4 v = *(const float4*)&src[c];
            wsb[r * 512 + (c >> 1)]     = packbf(v.x, v.y);
            wsb[r * 512 + (c >> 1) + 1] = packbf(v.z, v.w);
        }
    }
    if (tid < 32) cs[tid] = 0.f;
    __syncthreads();

    const int r0 = warp * 4;
    const uint32_t* wp0 = wsb + (r0 + 0) * 512;
    const uint32_t* wp1 = wsb + (r0 + 1) * 512;
    const uint32_t* wp2 = wsb + (r0 + 2) * 512;
    const uint32_t* wp3 = wsb + (r0 + 3) * 512;

    for (int t = 0; t < Tlen; t++) {
        if (t == 0) {
            for (int i = tid; i < 2048; i += 256) hsb[i] = 0u;
        } else {
            const uint4* hp = (const uint4*)(hbf + (size_t)t * (Bsz * Edim));
            uint4* hd = (uint4*)hsb;
            for (int i = tid; i < 512; i += 256) hd[i] = hp[i];
        }
        __syncthreads();

        unsigned long long acc[16];
#pragma unroll
        for (int i = 0; i < 16; i++) acc[i] = 0ull;

#pragma unroll 4
        for (int kp = lane; kp < 512; kp += 32) {
            unsigned long long W0 = bf2f2(wp0[kp]);
            unsigned long long W1 = bf2f2(wp1[kp]);
            unsigned long long W2 = bf2f2(wp2[kp]);
            unsigned long long W3 = bf2f2(wp3[kp]);
            unsigned long long H0 = bf2f2(hsb[kp]);
            unsigned long long H1 = bf2f2(hsb[512 + kp]);
            unsigned long long H2 = bf2f2(hsb[1024 + kp]);
            unsigned long long H3 = bf2f2(hsb[1536 + kp]);
            fma2(acc[ 0], W0, H0); fma2(acc[ 1], W0, H1); fma2(acc[ 2], W0, H2); fma2(acc[ 3], W0, H3);
            fma2(acc[ 4], W1, H0); fma2(acc[ 5], W1, H1); fma2(acc[ 6], W1, H2); fma2(acc[ 7], W1, H3);
            fma2(acc[ 8], W2, H0); fma2(acc[ 9], W2, H1); fma2(acc[10], W2, H2); fma2(acc[11], W2, H3);
            fma2(acc[12], W3, H0); fma2(acc[13], W3, H1); fma2(acc[14], W3, H2); fma2(acc[15], W3, H3);
        }

        float a[16];
#pragma unroll
        for (int i = 0; i < 16; i++) a[i] = f2sum(acc[i]);
#pragma unroll
        for (int off = 16; off; off >>= 1)
#pragma unroll
            for (int i = 0; i < 16; i++)
                a[i] += __shfl_down_sync(~0u, a[i], off);

        if (lane == 0) {
#pragma unroll
            for (int rr = 0; rr < 4; rr++) {
                int r = r0 + rr, g = r >> 3, j = r & 7;
#pragma unroll
                for (int b = 0; b < 4; b++)
                    garr[(g * 4 + b) * 8 + j] = a[rr * 4 + b];
            }
        }
        __syncthreads();

        if (tid < 32) {
            int b = tid >> 3, j = tid & 7, e = e0 + j;
            const float* gb = gih + ((size_t)t * Bsz + b) * GDIM;
            float gi = garr[(0 * 4 + b) * 8 + j] + gb[e];
            float gf = garr[(1 * 4 + b) * 8 + j] + gb[Edim + e];
            float gG = garr[(2 * 4 + b) * 8 + j] + gb[2 * Edim + e];
            float go = garr[(3 * 4 + b) * 8 + j] + gb[3 * Edim + e];
            float c = sigm(gf) * cs[tid] + sigm(gi) * tanh_acc(gG);
            cs[tid] = c;
            float hv = sigm(go) * tanh_acc(c);
            hbf[(size_t)(t + 1) * (Bsz * Edim) + b * Edim + e] = __float2bfloat16(hv);
        }
        __syncthreads();   // block's h-stores complete before the slot release

        // dedicated-waiter grid barrier
        unsigned int gen = (unsigned int)(t + 1);
        if (tid == 0) {
            __threadfence();
            st_rel(&g_slot[blk], gen);
        }
        if (blk == 0) {
            if (tid < NBLK) spin_acq(&g_slot[tid], gen);
            __syncthreads();
            if (tid == 0) { __threadfence(); st_rel(&g_rel2, gen); }
        } else {
            if (tid == 0) spin_acq(&g_rel2, gen);
            __syncthreads();
        }
    }
}

// ---------------- post-processing ----------------
__global__ void postprocess(float* __restrict__ out) {
    const int r = blockIdx.x;
    const int t_idx = r & (Tlen - 1);
    float* z = out + (size_t)r * Vdim;
    const int VV = Vdim - 1;
    const int tid = threadIdx.x;

    __shared__ float red[256];
    __shared__ float sh_shift, sh_eos;

    float mx = -3.402823466e38f;
    for (int v = tid; v < VV; v += 256) mx = fmaxf(mx, z[v]);
    red[tid] = mx; __syncthreads();
#pragma unroll
    for (int s = 128; s; s >>= 1) { if (tid < s) red[tid] = fmaxf(red[tid], red[tid + s]); __syncthreads(); }
    mx = red[0];
    __syncthreads();

    float sum = 0.f;
    for (int v = tid; v < VV; v += 256) sum += expf(z[v] - mx);
    red[tid] = sum; __syncthreads();
#pragma unroll
    for (int s = 128; s; s >>= 1) { if (tid < s) red[tid] += red[tid + s]; __syncthreads(); }

    if (tid == 0) {
        double lse = (double)mx + log((double)red[0]);
        double e   = (double)z[VV];
        double lsn = (-e < 0 ? -e : 0.0) - log1p(exp(-fabs(e)));
        double lsp = ( e < 0 ?  e : 0.0) - log1p(exp(-fabs(e)));
        double log_lb = (double)(t_idx + 1) * LOGB;
        double C1 = log_lb + lsn;
        double log_lb_eos = log(-expm1(log_lb)) + lsn;
        double d = log_lb_eos - lsp;
        double logsig_d = (d < 0 ? d : 0.0) - log1p(exp(-fabs(d)));
        double lpe = log_lb_eos - logsig_d;
        double m2 = fmax(C1, lpe);
        double Z  = m2 + log1p(exp(fmin(C1, lpe) - m2));
        sh_shift = (float)(C1 - lse - Z);
        sh_eos   = (float)(lpe - Z);
    }
    __syncthreads();

    float shift = sh_shift;
    for (int v = tid; v < VV; v += 256) z[v] += shift;
    if (tid == 0) z[VV] = sh_eos;
}

// ---------------- launcher ----------------
extern "C" void kernel_launch(void* const* d_in, const int* in_sizes, int n_in,
                              void* d_out, int out_size)
{
    (void)in_sizes; (void)n_in; (void)out_size;
    // 0:tokens 1:emb 2:Wproj 3:Wih0 4:Whh0 5:bih0 6:bhh0 7:Wih1 8:Whh1 9:bih1 10:bhh1
    const int*   tokens = (const int*)  d_in[0];
    const float* emb    = (const float*)d_in[1];
    const float* Wproj  = (const float*)d_in[2];
    const float* Wih0   = (const float*)d_in[3];
    const float* Whh0   = (const float*)d_in[4];
    const float* bih0   = (const float*)d_in[5];
    const float* bhh0   = (const float*)d_in[6];
    const float* Wih1   = (const float*)d_in[7];
    const float* Whh1   = (const float*)d_in[8];
    const float* bih1   = (const float*)d_in[9];
    const float* bhh1   = (const float*)d_in[10];
    float* out = (float*)d_out;

    __nv_bfloat16 *pxbf, *ph0bf, *ph1bf, *pw0, *pw1, *pwp;
    float *pg;
    cudaGetSymbolAddress((void**)&pxbf,  g_xbf);
    cudaGetSymbolAddress((void**)&pg,    g_gates);
    cudaGetSymbolAddress((void**)&ph0bf, g_h0bf);
    cudaGetSymbolAddress((void**)&ph1bf, g_h1bf);
    cudaGetSymbolAddress((void**)&pw0,   g_wih0bf);
    cudaGetSymbolAddress((void**)&pw1,   g_wih1bf);
    cudaGetSymbolAddress((void**)&pwp,   g_wprojbf);

    const int lstm_smem = (32 * 512 + 4 * 512) * 4 + (128 + 32) * 4;
    cudaFuncSetAttribute(lstm_layer, cudaFuncAttributeMaxDynamicSharedMemorySize, lstm_smem);
    const int gemm_smem = 128 * 40 * 2 * 2;   // 20480 B (mma layout; ffma needs 8448)
    cudaFuncSetAttribute(gemm_hybrid, cudaFuncAttributeMaxDynamicSharedMemorySize, gemm_smem);

    // 0. weight conversions
    f2bf_kernel<<<GDIM * Edim / 1024, 256>>>(Wih0, pw0, GDIM * Edim);
    f2bf_kernel<<<GDIM * Edim / 1024, 256>>>(Wih1, pw1, GDIM * Edim);
    f2bf_kernel<<<Vdim * (Edim / 1024), 256>>>(Wproj, pwp, Vdim * Edim);

    // 1. embedding
    embed_kernel<<<(MROWS * Edim / 4 + 255) / 256, 256>>>(tokens, emb);

    // 2. layer-0 input gates (hybrid mma+ffma)
    dim3 gg(MROWS / 128, GDIM / 128);       // (16, 32)
    gemm_hybrid<<<gg, 256, gemm_smem>>>(pxbf, pw0, pg, MROWS, GDIM, Edim, bih0, bhh0, 0);

    // 3. layer-0 recurrence
    bar_reset<<<1, 128>>>();
    lstm_layer<<<NBLK, 256, lstm_smem>>>(pg, Whh0, ph0bf);

    // 4. layer-1 input gates
    gemm_hybrid<<<gg, 256, gemm_smem>>>(ph0bf + Bsz * Edim, pw1, pg, MROWS, GDIM, Edim, bih1, bhh1, 0);

    // 5. layer-1 recurrence
    bar_reset<<<1, 128>>>();
    lstm_layer<<<NBLK, 256, lstm_smem>>>(pg, Whh1, ph1bf);

    // 6. projection (hybrid) -> d_out with [B,T] remap
    dim3 gp(MROWS / 128, Vdim / 128);       // (16, 250)
    gemm_hybrid<<<gp, 256, gemm_smem>>>(ph1bf + Bsz * Edim, pwp, out, MROWS, Vdim, Edim,
                                        nullptr, nullptr, 1);

    // 7. post-processing
    postprocess<<<MROWS, 256>>>(out);
}

// round 12
// speedup vs baseline: 1.6516x; 1.6516x over previous
#include <cuda_runtime.h>
#include <cuda_bf16.h>
#include <math.h>
#include <stdint.h>

#define Bsz  4
#define Tlen 512
#define Edim 1024
#define Vdim 32000
#define GDIM (4*Edim)           // 4096
#define MROWS (Tlen*Bsz)        // 2048
#define NBLK 128
#define LOGB (-1.0005003335835335e-3)

// ---------------- scratch ----------------
static __device__ __align__(16) __nv_bfloat16 g_xbf [MROWS * Edim];
static __device__ __align__(16) float g_gates[MROWS * GDIM];
static __device__ __align__(16) __nv_bfloat16 g_h0bf[(Tlen+1) * Bsz*Edim];
static __device__ __align__(16) __nv_bfloat16 g_h1bf[(Tlen+1) * Bsz*Edim];
static __device__ __align__(16) __nv_bfloat16 g_wih0bf[GDIM * Edim];
static __device__ __align__(16) __nv_bfloat16 g_wih1bf[GDIM * Edim];
static __device__ __align__(16) __nv_bfloat16 g_wprojbf[(size_t)Vdim * Edim];

// grid-barrier (proven round-6/9 version)
static __device__ unsigned int g_arrive;
static __device__ unsigned int g_release;
__global__ void bar_reset() { g_arrive = 0; g_release = 0; }

// ---------------- helpers ----------------
__device__ __forceinline__ float tanh_acc(float x) {
    float ax = fabsf(x);
    float t  = expf(-2.f * ax);
    float r  = (1.f - t) / (1.f + t);
    return copysignf(r, x);
}
__device__ __forceinline__ float sigm(float x) { return 1.f / (1.f + expf(-x)); }

__device__ __forceinline__ void grid_barrier_t0(unsigned int gen) {
    __threadfence();
    unsigned int prev = atomicAdd(&g_arrive, 1u);
    if (prev + 1u == gen * NBLK) {
        __threadfence();
        asm volatile("st.release.gpu.u32 [%0], %1;"
                     :: "l"(&g_release), "r"(gen) : "memory");
    } else {
        unsigned int v;
        do {
            asm volatile("ld.acquire.gpu.u32 %0, [%1];"
                         : "=r"(v) : "l"(&g_release) : "memory");
        } while (v < gen);
    }
}

__device__ __forceinline__ void fma2(unsigned long long& acc,
                                     unsigned long long a, unsigned long long b) {
    asm("fma.rn.f32x2 %0, %1, %2, %0;" : "+l"(acc) : "l"(a), "l"(b));
}
__device__ __forceinline__ float f2sum(unsigned long long acc) {
    uint32_t lo, hi;
    asm("mov.b64 {%0,%1}, %2;" : "=r"(lo), "=r"(hi) : "l"(acc));
    return __uint_as_float(lo) + __uint_as_float(hi);
}
__device__ __forceinline__ unsigned long long packf2(float a, float b) {
    unsigned long long r;
    asm("mov.b64 %0, {%1,%2};" : "=l"(r) : "f"(a), "f"(b));
    return r;
}
__device__ __forceinline__ uint32_t packbf(float a, float b) {
    __nv_bfloat162 t = __floats2bfloat162_rn(a, b);
    return *(uint32_t*)&t;
}

__device__ __forceinline__ void ldsm_x4(uint32_t& r0, uint32_t& r1, uint32_t& r2, uint32_t& r3,
                                        uint32_t addr) {
    asm volatile("ldmatrix.sync.aligned.m8n8.x4.shared.b16 {%0,%1,%2,%3}, [%4];"
                 : "=r"(r0), "=r"(r1), "=r"(r2), "=r"(r3) : "r"(addr));
}
__device__ __forceinline__ void mma_bf16(float c[4], const uint32_t a[4], const uint32_t b[2]) {
    asm volatile(
        "mma.sync.aligned.m16n8k16.row.col.f32.bf16.bf16.f32 "
        "{%0,%1,%2,%3}, {%4,%5,%6,%7}, {%8,%9}, {%0,%1,%2,%3};"
        : "+f"(c[0]), "+f"(c[1]), "+f"(c[2]), "+f"(c[3])
        : "r"(a[0]), "r"(a[1]), "r"(a[2]), "r"(a[3]), "r"(b[0]), "r"(b[1]));
}

// ---------------- fp32 -> bf16 ----------------
__global__ void f2bf_kernel(const float* __restrict__ s, __nv_bfloat16* __restrict__ d, int n) {
    int idx = (blockIdx.x * blockDim.x + threadIdx.x) * 4;
    if (idx >= n) return;
    float4 v = *(const float4*)(s + idx);
    uint2 p;
    p.x = packbf(v.x, v.y); p.y = packbf(v.z, v.w);
    *(uint2*)(d + idx) = p;
}

// ---------------- embedding ----------------
__global__ void embed_kernel(const int* __restrict__ tokens, const float* __restrict__ emb) {
    int id = blockIdx.x * blockDim.x + threadIdx.x;
    const int EV = Edim / 4;
    if (id >= MROWS * EV) return;
    int e4 = id % EV;
    int m  = id / EV;
    int b  = m & 3, t = m >> 2;
    int tok = tokens[b * Tlen + t];
    float4 v = ((const float4*)(emb + (size_t)tok * Edim))[e4];
    uint2 p; p.x = packbf(v.x, v.y); p.y = packbf(v.z, v.w);
    *(uint2*)(g_xbf + (size_t)id * 4) = p;
}

// ---------------- bf16 tensor-core GEMM (NT) — round-8 proven ----------------
__global__ __launch_bounds__(256)
void gemm_bf16_nt(const __nv_bfloat16* __restrict__ A, const __nv_bfloat16* __restrict__ B,
                  float* __restrict__ C, int M, int N, int K,
                  const float* __restrict__ bias1, const float* __restrict__ bias2,
                  int remap)
{
    __shared__ __align__(16) __nv_bfloat16 As[128 * 40];
    __shared__ __align__(16) __nv_bfloat16 Bs[128 * 40];
    const int tid  = threadIdx.x;
    const int wid  = tid >> 5, lane = tid & 31;
    const int g    = lane >> 2, tig = lane & 3;
    const int q    = lane >> 3, r = lane & 7;
    const int warp_m = (wid >> 2) * 64;
    const int warp_n = (wid & 3) * 32;
    const int row0 = blockIdx.x * 128;
    const int col0 = blockIdx.y * 128;

    const int ldr = tid >> 2;
    const int ldc = (tid & 3) * 8;

    const __nv_bfloat16* Ap0 = A + (size_t)(row0 + ldr) * K + ldc;
    const __nv_bfloat16* Ap1 = A + (size_t)(row0 + ldr + 64) * K + ldc;
    const __nv_bfloat16* Bp0 = B + (size_t)(col0 + ldr) * K + ldc;
    const __nv_bfloat16* Bp1 = B + (size_t)(col0 + ldr + 64) * K + ldc;

    const uint32_t as_base = (uint32_t)__cvta_generic_to_shared(As);
    const uint32_t bs_base = (uint32_t)__cvta_generic_to_shared(Bs);
    const uint32_t a_addr0 = as_base + (uint32_t)(((warp_m + (q & 1) * 8 + r) * 40 + (q >> 1) * 8) * 2);
    const uint32_t b_addr0 = bs_base + (uint32_t)(((warp_n + (q & 1) * 8 + r) * 40 + (q >> 1) * 8) * 2);

    float acc[16][4];
#pragma unroll
    for (int i = 0; i < 16; i++)
#pragma unroll
        for (int j = 0; j < 4; j++) acc[i][j] = 0.f;

    uint4 pa0 = *(const uint4*)Ap0;
    uint4 pa1 = *(const uint4*)Ap1;
    uint4 pb0 = *(const uint4*)Bp0;
    uint4 pb1 = *(const uint4*)Bp1;

    for (int kb = 0; kb < K; kb += 32) {
        *(uint4*)&As[ldr * 40 + ldc]        = pa0;
        *(uint4*)&As[(ldr + 64) * 40 + ldc] = pa1;
        *(uint4*)&Bs[ldr * 40 + ldc]        = pb0;
        *(uint4*)&Bs[(ldr + 64) * 40 + ldc] = pb1;
        __syncthreads();

        if (kb + 32 < K) {
            pa0 = *(const uint4*)(Ap0 + kb + 32);
            pa1 = *(const uint4*)(Ap1 + kb + 32);
            pb0 = *(const uint4*)(Bp0 + kb + 32);
            pb1 = *(const uint4*)(Bp1 + kb + 32);
        }

#pragma unroll
        for (int ks = 0; ks < 2; ks++) {
            uint32_t af[4][4], bf[4][2];
#pragma unroll
            for (int mt = 0; mt < 4; mt++)
                ldsm_x4(af[mt][0], af[mt][1], af[mt][2], af[mt][3],
                        a_addr0 + (uint32_t)((mt * 16 * 40 + ks * 16) * 2));
#pragma unroll
            for (int bt = 0; bt < 2; bt++) {
                uint32_t m0, m1, m2, m3;
                ldsm_x4(m0, m1, m2, m3,
                        b_addr0 + (uint32_t)((bt * 16 * 40 + ks * 16) * 2));
                bf[bt * 2 + 0][0] = m0; bf[bt * 2 + 1][0] = m1;
                bf[bt * 2 + 0][1] = m2; bf[bt * 2 + 1][1] = m3;
            }
#pragma unroll
            for (int mt = 0; mt < 4; mt++)
#pragma unroll
                for (int nt = 0; nt < 4; nt++)
                    mma_bf16(acc[mt * 4 + nt], af[mt], bf[nt]);
        }
        __syncthreads();
    }

#pragma unroll
    for (int mt = 0; mt < 4; mt++) {
        int m0 = row0 + warp_m + mt * 16 + g;
        int m1 = m0 + 8;
        int r0 = remap ? ((m0 & 3) * Tlen + (m0 >> 2)) : m0;
        int r1 = remap ? ((m1 & 3) * Tlen + (m1 >> 2)) : m1;
#pragma unroll
        for (int nt = 0; nt < 4; nt++) {
            int n = col0 + warp_n + nt * 8 + tig * 2;
            float bv0 = 0.f, bv1 = 0.f;
            if (bias1) { bv0 += bias1[n]; bv1 += bias1[n + 1]; }
            if (bias2) { bv0 += bias2[n]; bv1 += bias2[n + 1]; }
            float* c = acc[mt * 4 + nt];
            *(float2*)&C[(size_t)r0 * N + n] = make_float2(c[0] + bv0, c[1] + bv1);
            *(float2*)&C[(size_t)r1 * N + n] = make_float2(c[2] + bv0, c[3] + bv1);
        }
    }
}

// ---------------- persistent LSTM layer: register-resident Whh (fp32x2),
// fp32 h staging, f32x2 packed FMA ----------------
__global__ void __launch_bounds__(256, 1)
lstm_layer(const float* __restrict__ gih,          // [T,B,4E] fp32 gates (+bias)
           const float* __restrict__ Whh,          // [4E,E] fp32
           __nv_bfloat16* __restrict__ hbf)        // [T+1,B,E] bf16; slots 1..T written
{
    __shared__ __align__(16) float hs[4 * Edim];   // fp32 h_prev (16KB)
    __shared__ float garr[128];                    // [4g][4b][8j]
    __shared__ float cs[32];                       // [4b][8j]

    const int blk  = blockIdx.x;
    const int e0   = blk * 8;
    const int tid  = threadIdx.x;
    const int warp = tid >> 5;
    const int lane = tid & 31;

    // Whh rows for this warp -> registers as f32x2 pairs.
    // row r = warp*4+rr maps to global row g*Edim + e0 + j (g=r>>3, j=r&7).
    unsigned long long wreg[4][16];
#pragma unroll
    for (int rr = 0; rr < 4; rr++) {
        int r = warp * 4 + rr, g = r >> 3, j = r & 7;
        const float* src = Whh + (size_t)(g * Edim + e0 + j) * Edim;
#pragma unroll
        for (int jj = 0; jj < 16; jj++) {
            int kp = lane + 32 * jj;               // k-pair index (0..511)
            float2 v = *(const float2*)&src[kp * 2];
            wreg[rr][jj] = packf2(v.x, v.y);
        }
    }
    if (tid < 32) cs[tid] = 0.f;
    __syncthreads();

    for (int t = 0; t < Tlen; t++) {
        // stage h_prev as fp32 (expand bf16 once here, not per-use)
        if (t == 0) {
            for (int i = tid; i < 4 * Edim; i += 256) hs[i] = 0.f;
        } else {
            const uint4* hp = (const uint4*)(hbf + (size_t)t * (Bsz * Edim));
#pragma unroll
            for (int i = tid; i < 512; i += 256) {
                uint4 p = hp[i];                   // 8 bf16
                float* d = hs + i * 8;
                d[0] = __uint_as_float(p.x << 16);
                d[1] = __uint_as_float(p.x & 0xFFFF0000u);
                d[2] = __uint_as_float(p.y << 16);
                d[3] = __uint_as_float(p.y & 0xFFFF0000u);
                d[4] = __uint_as_float(p.z << 16);
                d[5] = __uint_as_float(p.z & 0xFFFF0000u);
                d[6] = __uint_as_float(p.w << 16);
                d[7] = __uint_as_float(p.w & 0xFFFF0000u);
            }
        }
        __syncthreads();

        unsigned long long acc[16];
#pragma unroll
        for (int i = 0; i < 16; i++) acc[i] = 0ull;

#pragma unroll
        for (int jj = 0; jj < 16; jj++) {
            int kp = lane + 32 * jj;
            unsigned long long H0 = *(const unsigned long long*)&hs[kp * 2];
            unsigned long long H1 = *(const unsigned long long*)&hs[Edim + kp * 2];
            unsigned long long H2 = *(const unsigned long long*)&hs[2 * Edim + kp * 2];
            unsigned long long H3 = *(const unsigned long long*)&hs[3 * Edim + kp * 2];
            fma2(acc[ 0], wreg[0][jj], H0); fma2(acc[ 1], wreg[0][jj], H1);
            fma2(acc[ 2], wreg[0][jj], H2); fma2(acc[ 3], wreg[0][jj], H3);
            fma2(acc[ 4], wreg[1][jj], H0); fma2(acc[ 5], wreg[1][jj], H1);
            fma2(acc[ 6], wreg[1][jj], H2); fma2(acc[ 7], wreg[1][jj], H3);
            fma2(acc[ 8], wreg[2][jj], H0); fma2(acc[ 9], wreg[2][jj], H1);
            fma2(acc[10], wreg[2][jj], H2); fma2(acc[11], wreg[2][jj], H3);
            fma2(acc[12], wreg[3][jj], H0); fma2(acc[13], wreg[3][jj], H1);
            fma2(acc[14], wreg[3][jj], H2); fma2(acc[15], wreg[3][jj], H3);
        }

        float a[16];
#pragma unroll
        for (int i = 0; i < 16; i++) a[i] = f2sum(acc[i]);
#pragma unroll
        for (int off = 16; off; off >>= 1)
#pragma unroll
            for (int i = 0; i < 16; i++)
                a[i] += __shfl_down_sync(~0u, a[i], off);

        if (lane == 0) {
#pragma unroll
            for (int rr = 0; rr < 4; rr++) {
                int r = warp * 4 + rr, g = r >> 3, j = r & 7;
#pragma unroll
                for (int b = 0; b < 4; b++)
                    garr[(g * 4 + b) * 8 + j] = a[rr * 4 + b];
            }
        }
        __syncthreads();

        if (tid < 32) {
            int b = tid >> 3, j = tid & 7, e = e0 + j;
            const float* gb = gih + ((size_t)t * Bsz + b) * GDIM;
            float gi = garr[(0 * 4 + b) * 8 + j] + gb[e];
            float gf = garr[(1 * 4 + b) * 8 + j] + gb[Edim + e];
            float gG = garr[(2 * 4 + b) * 8 + j] + gb[2 * Edim + e];
            float go = garr[(3 * 4 + b) * 8 + j] + gb[3 * Edim + e];
            float c = sigm(gf) * cs[tid] + sigm(gi) * tanh_acc(gG);
            cs[tid] = c;
            float hv = sigm(go) * tanh_acc(c);
            hbf[(size_t)(t + 1) * (Bsz * Edim) + b * Edim + e] = __float2bfloat16(hv);
        }
        __syncthreads();

        if (tid == 0) grid_barrier_t0((unsigned int)(t + 1));
        __syncthreads();
    }
}

// ---------------- post-processing: online 2-pass, float4 ----------------
__global__ void postprocess(float* __restrict__ out) {
    const int r = blockIdx.x;
    const int t_idx = r & (Tlen - 1);
    float* z = out + (size_t)r * Vdim;
    const int tid = threadIdx.x;

    __shared__ float redm[256];
    __shared__ float reds[256];
    __shared__ float sh_shift, sh_eos;

    // online max+sum in one read pass (float4; vocab = 31999 = 7999*4 + 3)
    float m = -3.402823466e38f, s = 0.f;
    const float4* z4 = (const float4*)z;
    for (int i = tid; i < 7999; i += 256) {
        float4 v = z4[i];
        float mv = fmaxf(fmaxf(v.x, v.y), fmaxf(v.z, v.w));
        float m2 = fmaxf(m, mv);
        s = s * expf(m - m2)
          + expf(v.x - m2) + expf(v.y - m2) + expf(v.z - m2) + expf(v.w - m2);
        m = m2;
    }
    if (tid < 3) {
        float x = z[31996 + tid];
        float m2 = fmaxf(m, x);
        s = s * expf(m - m2) + expf(x - m2);
        m = m2;
    }
    redm[tid] = m; reds[tid] = s;
    __syncthreads();
#pragma unroll
    for (int st = 128; st; st >>= 1) {
        if (tid < st) {
            float mo = redm[tid], so = reds[tid];
            float mn = redm[tid + st], sn = reds[tid + st];
            float mm = fmaxf(mo, mn);
            redm[tid] = mm;
            reds[tid] = so * expf(mo - mm) + sn * expf(mn - mm);
        }
        __syncthreads();
    }

    if (tid == 0) {
        double lse = (double)redm[0] + log((double)reds[0]);
        double e   = (double)z[Vdim - 1];
        double lsn = (-e < 0 ? -e : 0.0) - log1p(exp(-fabs(e)));  // log_sigmoid(-e)
        double lsp = ( e < 0 ?  e : 0.0) - log1p(exp(-fabs(e)));  // log_sigmoid(e)
        double log_lb = (double)(t_idx + 1) * LOGB;
        double C1 = log_lb + lsn;
        double log_lb_eos = log(-expm1(log_lb)) + lsn;
        double d = log_lb_eos - lsp;
        double logsig_d = (d < 0 ? d : 0.0) - log1p(exp(-fabs(d)));
        double lpe = log_lb_eos - logsig_d;
        double m2 = fmax(C1, lpe);
        double Z  = m2 + log1p(exp(fmin(C1, lpe) - m2));
        sh_shift = (float)(C1 - lse - Z);
        sh_eos   = (float)(lpe - Z);
    }
    __syncthreads();

    float shift = sh_shift;
    float4* zw = (float4*)z;
    for (int i = tid; i < 7999; i += 256) {
        float4 v = zw[i];
        v.x += shift; v.y += shift; v.z += shift; v.w += shift;
        zw[i] = v;
    }
    if (tid < 3) z[31996 + tid] += shift;
    if (tid == 0) z[Vdim - 1] = sh_eos;
}

// ---------------- launcher ----------------
extern "C" void kernel_launch(void* const* d_in, const int* in_sizes, int n_in,
                              void* d_out, int out_size)
{
    (void)in_sizes; (void)n_in; (void)out_size;
    // 0:tokens 1:emb 2:Wproj 3:Wih0 4:Whh0 5:bih0 6:bhh0 7:Wih1 8:Whh1 9:bih1 10:bhh1
    const int*   tokens = (const int*)  d_in[0];
    const float* emb    = (const float*)d_in[1];
    const float* Wproj  = (const float*)d_in[2];
    const float* Wih0   = (const float*)d_in[3];
    const float* Whh0   = (const float*)d_in[4];
    const float* bih0   = (const float*)d_in[5];
    const float* bhh0   = (const float*)d_in[6];
    const float* Wih1   = (const float*)d_in[7];
    const float* Whh1   = (const float*)d_in[8];
    const float* bih1   = (const float*)d_in[9];
    const float* bhh1   = (const float*)d_in[10];
    float* out = (float*)d_out;

    __nv_bfloat16 *pxbf, *ph0bf, *ph1bf, *pw0, *pw1, *pwp;
    float *pg;
    cudaGetSymbolAddress((void**)&pxbf,  g_xbf);
    cudaGetSymbolAddress((void**)&pg,    g_gates);
    cudaGetSymbolAddress((void**)&ph0bf, g_h0bf);
    cudaGetSymbolAddress((void**)&ph1bf, g_h1bf);
    cudaGetSymbolAddress((void**)&pw0,   g_wih0bf);
    cudaGetSymbolAddress((void**)&pw1,   g_wih1bf);
    cudaGetSymbolAddress((void**)&pwp,   g_wprojbf);

    // 0. weight conversions
    f2bf_kernel<<<GDIM * Edim / 1024, 256>>>(Wih0, pw0, GDIM * Edim);
    f2bf_kernel<<<GDIM * Edim / 1024, 256>>>(Wih1, pw1, GDIM * Edim);
    f2bf_kernel<<<Vdim * (Edim / 1024), 256>>>(Wproj, pwp, Vdim * Edim);

    // 1. embedding
    embed_kernel<<<(MROWS * Edim / 4 + 255) / 256, 256>>>(tokens, emb);

    // 2. layer-0 input gates (bf16 tensor cores)
    dim3 gg(MROWS / 128, GDIM / 128);
    gemm_bf16_nt<<<gg, 256>>>(pxbf, pw0, pg, MROWS, GDIM, Edim, bih0, bhh0, 0);

    // 3. layer-0 recurrence
    bar_reset<<<1, 1>>>();
    lstm_layer<<<NBLK, 256>>>(pg, Whh0, ph0bf);

    // 4. layer-1 input gates
    gemm_bf16_nt<<<gg, 256>>>(ph0bf + Bsz * Edim, pw1, pg, MROWS, GDIM, Edim, bih1, bhh1, 0);

    // 5. layer-1 recurrence
    bar_reset<<<1, 1>>>();
    lstm_layer<<<NBLK, 256>>>(pg, Whh1, ph1bf);

    // 6. projection -> d_out with [B,T] remap
    dim3 gp(MROWS / 128, Vdim / 128);
    gemm_bf16_nt<<<gp, 256>>>(ph1bf + Bsz * Edim, pwp, out, MROWS, Vdim, Edim,
                              nullptr, nullptr, 1);

    // 7. post-processing
    postprocess<<<MROWS, 256>>>(out);
}